// round 16
// baseline (speedup 1.0000x reference)
#include <cuda_runtime.h>
#include <cuda_fp16.h>
#include <stdint.h>
#include <math.h>

// ===========================================================================
// CrossAttention B=8, S=2048, D=512 (single head, fp32 I/O).
// All GEMMs on mma.sync (HMMA fp16, fp32 accum), 1-term, compact f16.
// 256x128 CTA tile, 8 warps (64x64 warp tiles), 1 CTA/SM: amortizes
// per-k-iter fixed costs (barriers, LDSM crossbar, issue slots) over 2x
// the MACs -- R13/R14/R15 showed occupancy and ILP are not the limiter.
// Algebraic fusions: W'=Wo@Wv fold; RoPE in Q/K epilogue via feature perm;
// V' epilogue writes Vt transposed (conflict-free staging).
// ===========================================================================

#define BATCH 8
#define SEQ   2048
#define DIM   512
#define MS    (BATCH * SEQ)     // 16384
#define HALFD (DIM / 2)

#define BM 256
#define BN 128
#define BKE 64                          // fp16 elems per k-chunk (128 bytes)
#define BKB 128                         // bytes per smem row
#define STAGES 3
#define A_TILE_BYTES (BM * BKB)         // 32768
#define B_TILE_BYTES (BN * BKB)         // 16384
#define STAGE_BYTES (A_TILE_BYTES + B_TILE_BYTES)  // 49152
#define SMEM_G (STAGES * STAGE_BYTES)   // 147456 -> 1 CTA/SM

// --------------------------- device scratch -------------------------------
__device__ __align__(1024) __half g_h1s[(size_t)MS * DIM];
__device__ __align__(1024) __half g_h2s[(size_t)MS * DIM];
__device__ __align__(1024) __half g_Wqs[(size_t)DIM * DIM];   // permuted rows
__device__ __align__(1024) __half g_Wks[(size_t)DIM * DIM];   // permuted rows
__device__ __align__(1024) __half g_Wps[(size_t)DIM * DIM];   // W' = Wo@Wv
__device__ __align__(1024) float  g_cb[DIM];                  // Wo@bv
__device__ __align__(1024) float2 g_tab[(size_t)SEQ * HALFD]; // (cos,sin)[s][c]
__device__ __align__(1024) __half g_Qs[(size_t)MS * DIM];     // permuted features
__device__ __align__(1024) __half g_Ks[(size_t)MS * DIM];     // permuted features
__device__ __align__(1024) __half g_Vts[(size_t)BATCH * DIM * SEQ];
__device__ __align__(1024) __half g_E16[(size_t)BATCH * SEQ * SEQ];
__device__ __align__(1024) __half g_Es[(size_t)BATCH * SEQ * SEQ];

// --------------------------- PTX helpers -----------------------------------
__device__ __forceinline__ uint32_t smem_u32(const void* p) {
    uint32_t a;
    asm("{ .reg .u64 t; cvta.to.shared.u64 t, %1; cvt.u32.u64 %0, t; }"
        : "=r"(a) : "l"(p));
    return a;
}
__device__ __forceinline__ void cp_async16(uint32_t dst, const void* src) {
    asm volatile("cp.async.cg.shared.global [%0], [%1], 16;" :: "r"(dst), "l"(src));
}
__device__ __forceinline__ void cp_commit() {
    asm volatile("cp.async.commit_group;" ::: "memory");
}
template <int N> __device__ __forceinline__ void cp_wait() {
    asm volatile("cp.async.wait_group %0;" :: "n"(N) : "memory");
}
__device__ __forceinline__ void ldsm4(uint32_t& r0, uint32_t& r1, uint32_t& r2,
                                      uint32_t& r3, uint32_t a) {
    asm volatile("ldmatrix.sync.aligned.m8n8.x4.shared.b16 {%0,%1,%2,%3}, [%4];"
                 : "=r"(r0), "=r"(r1), "=r"(r2), "=r"(r3) : "r"(a));
}
__device__ __forceinline__ void mma16816(float* d, const uint32_t* a,
                                         uint32_t b0, uint32_t b1) {
    asm volatile(
        "mma.sync.aligned.m16n8k16.row.col.f32.f16.f16.f32 "
        "{%0,%1,%2,%3}, {%4,%5,%6,%7}, {%8,%9}, {%0,%1,%2,%3};"
        : "+f"(d[0]), "+f"(d[1]), "+f"(d[2]), "+f"(d[3])
        : "r"(a[0]), "r"(a[1]), "r"(a[2]), "r"(a[3]), "r"(b0), "r"(b1));
}
__device__ __forceinline__ uint32_t sw128(uint32_t off) {
    return off ^ ((off >> 3) & 0x70);
}

// --------------------------- GEMM core (1-term) -----------------------------
// NT: C[m,n] = alpha * A[m,:].B[n,:] + bias[n]
// EPI: 0 = fp32 out, 1 = f16 out, 2 = f16 out with rope rotation (pair cols),
//      3 = f16 out written TRANSPOSED into Vt[B*DIM, SEQ] via smem staging.
// 8 warps: wm = wid&3 (M, 64 rows), wn = wid>>2 (N, 64 cols). acc 128 f32.
template <int EPI>
__device__ __forceinline__ void gemm_core1(
    const __half* __restrict__ A, const __half* __restrict__ B,
    void* __restrict__ Cv, const float* __restrict__ bias,
    const float2* __restrict__ tab,
    int Kp, int ldC, float alpha, int m0, int n0, char* smem)
{
    const int tid  = threadIdx.x;
    const int wid  = tid >> 5;
    const int lane = tid & 31;
    const int wm   = wid & 3;
    const int wn   = wid >> 2;
    const uint32_t smb = smem_u32(smem);
    const int chunks = Kp / BKE;

    auto issue = [&](int it) {
        const long long k0 = (long long)it * BKE;
        const uint32_t sb = smb + (it % STAGES) * STAGE_BYTES;
        #pragma unroll
        for (int i = 0; i < 8; i++) {               // A: 2048 float4
            const int id = tid * 8 + i;
            const int r = id >> 3, c = id & 7;
            const uint32_t off = sw128((uint32_t)(r * BKB + c * 16));
            cp_async16(sb + off, A + (long long)r * Kp + k0 + c * 8);
        }
        #pragma unroll
        for (int i = 0; i < 4; i++) {               // B: 1024 float4
            const int id = tid * 4 + i;
            const int r = id >> 3, c = id & 7;
            const uint32_t off = sw128((uint32_t)(r * BKB + c * 16));
            cp_async16(sb + A_TILE_BYTES + off, B + (long long)r * Kp + k0 + c * 8);
        }
        cp_commit();
    };

    float acc[4][8][4] = {};
    const int aRowBase = wm * 64;
    const int bRowBase = wn * 64;
    const int lrow = lane & 15;
    const int lkc  = lane >> 4;

    const int prol = (chunks < STAGES - 1) ? chunks : (STAGES - 1);
    for (int it = 0; it < prol; it++) issue(it);

    for (int it = 0; it < chunks; it++) {
        if (it < chunks - 1) cp_wait<STAGES - 2>(); else cp_wait<0>();
        __syncthreads();
        if (it + STAGES - 1 < chunks) issue(it + STAGES - 1);

        const uint32_t sA = smb + (it % STAGES) * STAGE_BYTES;
        const uint32_t sB = sA + A_TILE_BYTES;

        #pragma unroll
        for (int ks = 0; ks < 4; ks++) {
            uint32_t a[4][4], b[4][4];
            #pragma unroll
            for (int mi = 0; mi < 4; mi++) {
                const int row = aRowBase + mi * 16 + lrow;
                const uint32_t off = sw128((uint32_t)(row * BKB + ks * 32 + lkc * 16));
                ldsm4(a[mi][0], a[mi][1], a[mi][2], a[mi][3], sA + off);
            }
            #pragma unroll
            for (int nt = 0; nt < 4; nt++) {
                const int row = bRowBase + nt * 16 + lrow;
                const uint32_t off = sw128((uint32_t)(row * BKB + ks * 32 + lkc * 16));
                ldsm4(b[nt][0], b[nt][1], b[nt][2], b[nt][3], sB + off);
            }
            #pragma unroll
            for (int mi = 0; mi < 4; mi++)
                #pragma unroll
                for (int nt = 0; nt < 4; nt++) {
                    mma16816(acc[mi][nt * 2],     a[mi], b[nt][0], b[nt][2]);
                    mma16816(acc[mi][nt * 2 + 1], a[mi], b[nt][1], b[nt][3]);
                }
        }
    }

    if (EPI == 3) {
        // Stage f16 tile TRANSPOSED in smem (sm[n][m], PR=264 halves), then
        // coalesced write to Vt[B*DIM, SEQ]. All cp.async complete (wait<0>).
        __syncthreads();
        __half* sm = (__half*)smem;
        const int PR = 264;                    // 128 cols x 264 halves = 67.6KB
        #pragma unroll
        for (int mi = 0; mi < 4; mi++) {
            const int rl = wm * 64 + mi * 16 + (lane >> 2);
            #pragma unroll
            for (int nj = 0; nj < 8; nj++) {
                const int cl = wn * 64 + nj * 8 + (lane & 3) * 2;
                float b0 = bias[n0 + cl];
                float b1 = bias[n0 + cl + 1];
                sm[cl * PR + rl]           = __float2half(acc[mi][nj][0] + b0);
                sm[(cl + 1) * PR + rl]     = __float2half(acc[mi][nj][1] + b1);
                sm[cl * PR + rl + 8]       = __float2half(acc[mi][nj][2] + b0);
                sm[(cl + 1) * PR + rl + 8] = __float2half(acc[mi][nj][3] + b1);
            }
        }
        __syncthreads();
        __half* Vt = (__half*)Cv;
        const int bz = m0 >> 11;               // batch (m0 / SEQ)
        const int s0 = m0 & (SEQ - 1);
        #pragma unroll
        for (int jj = 0; jj < 16; jj++) {
            const int j = wid * 16 + jj;       // feature col 0..127
            #pragma unroll
            for (int hh = 0; hh < 2; hh++) {   // 256 rows in two halves
                const int rbase = hh * 128 + lane * 4;
                __half t0 = sm[j * PR + rbase + 0];
                __half t1 = sm[j * PR + rbase + 1];
                __half t2 = sm[j * PR + rbase + 2];
                __half t3 = sm[j * PR + rbase + 3];
                uint2 u;
                __half2 h01 = __halves2half2(t0, t1);
                __half2 h23 = __halves2half2(t2, t3);
                u.x = *reinterpret_cast<uint32_t*>(&h01);
                u.y = *reinterpret_cast<uint32_t*>(&h23);
                *reinterpret_cast<uint2*>(Vt + (size_t)bz * DIM * SEQ
                                          + (size_t)(n0 + j) * SEQ + s0 + rbase) = u;
            }
        }
        return;
    }

    #pragma unroll
    for (int mi = 0; mi < 4; mi++) {
        const int r = m0 + wm * 64 + mi * 16 + (lane >> 2);
        const int s0 = r & (SEQ - 1);
        const int s1 = (r + 8) & (SEQ - 1);
        #pragma unroll
        for (int nj = 0; nj < 8; nj++) {
            const int cidx = n0 + wn * 64 + nj * 8 + (lane & 3) * 2;
            if (EPI == 2) {
                const int c = cidx >> 1;
                float b0 = bias ? bias[c] : 0.f;
                float b1 = bias ? bias[c + HALFD] : 0.f;
                float x0 = acc[mi][nj][0] + b0;
                float x1 = acc[mi][nj][1] + b1;
                float x2 = acc[mi][nj][2] + b0;
                float x3 = acc[mi][nj][3] + b1;
                float2 cs0 = tab[(size_t)s0 * HALFD + c];
                float2 cs1 = tab[(size_t)s1 * HALFD + c];
                float y0 = x0 * cs0.x - x1 * cs0.y;
                float y1 = x1 * cs0.x + x0 * cs0.y;
                float y2 = x2 * cs1.x - x3 * cs1.y;
                float y3 = x3 * cs1.x + x2 * cs1.y;
                __half* Ch = (__half*)Cv;
                *reinterpret_cast<__half2*>(Ch + (long long)r * ldC + cidx)
                    = __floats2half2_rn(y0, y1);
                *reinterpret_cast<__half2*>(Ch + (long long)(r + 8) * ldC + cidx)
                    = __floats2half2_rn(y2, y3);
            } else {
                float b0 = bias ? bias[cidx] : 0.f;
                float b1 = bias ? bias[cidx + 1] : 0.f;
                float x0 = acc[mi][nj][0] * alpha + b0;
                float x1 = acc[mi][nj][1] * alpha + b1;
                float x2 = acc[mi][nj][2] * alpha + b0;
                float x3 = acc[mi][nj][3] * alpha + b1;
                if (EPI == 0) {
                    float* Cf = (float*)Cv;
                    *reinterpret_cast<float2*>(Cf + (long long)r * ldC + cidx)
                        = make_float2(x0, x1);
                    *reinterpret_cast<float2*>(Cf + (long long)(r + 8) * ldC + cidx)
                        = make_float2(x2, x3);
                } else {
                    __half* Ch = (__half*)Cv;
                    *reinterpret_cast<__half2*>(Ch + (long long)r * ldC + cidx)
                        = __floats2half2_rn(x0, x1);
                    *reinterpret_cast<__half2*>(Ch + (long long)(r + 8) * ldC + cidx)
                        = __floats2half2_rn(x2, x3);
                }
            }
        }
    }
}

// Generic batched GEMM (EPI 0 = fp32 out, 1 = f16 out), 1 CTA/SM.
template <int EPI>
__global__ __launch_bounds__(256, 1) void gemm1(
    const __half* __restrict__ A, const __half* __restrict__ B,
    void* __restrict__ C, const float* __restrict__ bias,
    int Kp, int ldC, int aRowsPerB, int bRowsPerB, long long cPerB, float alpha)
{
    extern __shared__ __align__(1024) char smem[];
    const __half* Ab = A + ((long long)blockIdx.z * aRowsPerB + (long long)blockIdx.y * BM) * Kp;
    const __half* Bb = B + ((long long)blockIdx.z * bRowsPerB + (long long)blockIdx.x * BN) * Kp;
    void* Cb = (EPI == 0)
        ? (void*)((float*)C + (long long)blockIdx.z * cPerB)
        : (void*)((__half*)C + (long long)blockIdx.z * cPerB);
    gemm_core1<EPI>(Ab, Bb, Cb, bias, nullptr, Kp, ldC, alpha,
                    blockIdx.y * BM, blockIdx.x * BN, smem);
}

// Fused Q/K/V' projections. z=0: Q=rope(h1@Wq^T+bq); z=1: K likewise;
// z=2: Vt = transpose(h2@W'^T + cb0) written directly.
__global__ __launch_bounds__(256, 1) void gemm_qkv(
    const __half* __restrict__ h1s, const __half* __restrict__ h2s,
    const __half* __restrict__ Wq, const __half* __restrict__ Wk,
    const __half* __restrict__ Wp,
    __half* __restrict__ Qs, __half* __restrict__ Ks, __half* __restrict__ Vts,
    const float* __restrict__ bq, const float* __restrict__ bk,
    const float* __restrict__ cb0, const float2* __restrict__ tab)
{
    extern __shared__ __align__(1024) char smem[];
    const int m0 = blockIdx.y * BM, n0 = blockIdx.x * BN;
    if (blockIdx.z == 2) {
        const __half* A = h2s + (long long)m0 * DIM;
        const __half* B = Wp + (long long)n0 * DIM;
        gemm_core1<3>(A, B, Vts, cb0, nullptr, DIM, 0, 1.0f, m0, n0, smem);
    } else {
        const __half* A = (blockIdx.z == 0 ? h1s : h2s) + (long long)m0 * DIM;
        const __half* B = (blockIdx.z == 0 ? Wq : Wk) + (long long)n0 * DIM;
        __half* C = blockIdx.z == 0 ? Qs : Ks;
        const float* bias = blockIdx.z == 0 ? bq : bk;
        gemm_core1<2>(A, B, C, bias, tab, DIM, DIM, 1.0f, m0, n0, smem);
    }
}

// ---------------- weight folding + cbias (fp32 exact), one launch ----------
__global__ __launch_bounds__(256) void wfold_kernel(
    const float* __restrict__ Wo, const float* __restrict__ Wv,
    const float* __restrict__ bv,
    __half* __restrict__ Wps, float* __restrict__ cb)
{
    const int t = threadIdx.x;
    if (blockIdx.y == DIM / 64) {
        const int w = t >> 5, lane = t & 31;
        #pragma unroll
        for (int k = 0; k < 8; k++) {
            const int e = blockIdx.x * 64 + w + k * 8;
            float s = 0.f;
            for (int d = lane; d < DIM; d += 32) s += Wo[e * DIM + d] * bv[d];
            #pragma unroll
            for (int off = 16; off; off >>= 1) s += __shfl_xor_sync(0xffffffffu, s, off);
            if (lane == 0) cb[e] = s;
        }
        return;
    }
    __shared__ float As[16][64];
    __shared__ float Bs[16][64];
    const int tx = t & 15, ty = t >> 4;
    const int e0 = blockIdx.y * 64;
    const int c0 = blockIdx.x * 64;

    float acc[4][4] = {};
    for (int d0 = 0; d0 < DIM; d0 += 16) {
        #pragma unroll
        for (int i = 0; i < 4; i++) {
            int id = t * 4 + i;
            int m = id >> 4, dd = id & 15;
            As[dd][m] = Wo[(e0 + m) * DIM + d0 + dd];
            int col = id & 63, row = id >> 6;
            Bs[row][col] = Wv[(d0 + row) * DIM + c0 + col];
        }
        __syncthreads();
        #pragma unroll
        for (int dd = 0; dd < 16; dd++) {
            float a[4], b[4];
            #pragma unroll
            for (int u = 0; u < 4; u++) { a[u] = As[dd][ty * 4 + u]; b[u] = Bs[dd][tx * 4 + u]; }
            #pragma unroll
            for (int x = 0; x < 4; x++)
                #pragma unroll
                for (int y = 0; y < 4; y++)
                    acc[x][y] = fmaf(a[x], b[y], acc[x][y]);
        }
        __syncthreads();
    }
    #pragma unroll
    for (int x = 0; x < 4; x++)
        #pragma unroll
        for (int y = 0; y < 4; y++)
            Wps[(size_t)(e0 + ty * 4 + x) * DIM + c0 + tx * 4 + y] = __float2half(acc[x][y]);
}

// ---------------- prep: h converts + permuted W converts + rope table ------
#define N4_H  ((long long)MS * DIM / 4)
#define N4_W  ((long long)DIM * DIM / 4)
#define N_TAB ((long long)SEQ * HALFD)
#define PREP_TOTAL (2 * N4_H + 2 * N4_W + N_TAB)

__global__ void prep_kernel(const float* __restrict__ h1, const float* __restrict__ h2,
                            const float* __restrict__ wq, const float* __restrict__ wk,
                            __half* __restrict__ h1s, __half* __restrict__ h2s,
                            __half* __restrict__ yq, __half* __restrict__ yk,
                            float2* __restrict__ tab)
{
    long long i = (long long)blockIdx.x * blockDim.x + threadIdx.x;
    if (i < 2 * N4_H) {
        const float* src = (i < N4_H) ? h1 : h2;
        __half* dst = (i < N4_H) ? h1s : h2s;
        long long k = (i < N4_H) ? i : i - N4_H;
        float4 v = reinterpret_cast<const float4*>(src)[k];
        reinterpret_cast<__half2*>(dst)[k * 2]     = __floats2half2_rn(v.x, v.y);
        reinterpret_cast<__half2*>(dst)[k * 2 + 1] = __floats2half2_rn(v.z, v.w);
        return;
    }
    i -= 2 * N4_H;
    if (i < 2 * N4_W) {
        const float* src = (i < N4_W) ? wq : wk;
        __half* dst = (i < N4_W) ? yq : yk;
        long long k = (i < N4_W) ? i : i - N4_W;
        int p = (int)(k / (DIM / 4));
        int d4 = (int)(k % (DIM / 4));
        int orig = (p & 1) ? (p >> 1) + HALFD : (p >> 1);
        float4 v = reinterpret_cast<const float4*>(src + (size_t)orig * DIM)[d4];
        __half2* o = reinterpret_cast<__half2*>(dst + (size_t)p * DIM) + d4 * 2;
        o[0] = __floats2half2_rn(v.x, v.y);
        o[1] = __floats2half2_rn(v.z, v.w);
        return;
    }
    i -= 2 * N4_W;
    if (i < N_TAB) {
        int c = (int)(i % HALFD);
        int s = (int)(i / HALFD);
        const float kNegLog2Base = -13.287712379549449f / 256.0f;
        float invf = exp2f((float)c * kNegLog2Base);
        float sn, cs;
        sincosf((float)s * invf, &sn, &cs);
        tab[i] = make_float2(cs, sn);
    }
}

// ---------------- softmax (f16 in/out, 8 halves/thread) ---------------------
__global__ __launch_bounds__(256) void softmax_h_kernel(const __half* __restrict__ E,
                                                        __half* __restrict__ Es)
{
    const int t = threadIdx.x;
    const uint2* pin = reinterpret_cast<const uint2*>(E + (size_t)blockIdx.x * SEQ);
    uint2* pout = reinterpret_cast<uint2*>(Es + (size_t)blockIdx.x * SEQ);

    uint2 u0 = pin[t];
    uint2 u1 = pin[t + 256];
    float v[8];
    {
        float2 f;
        f = __half22float2(*reinterpret_cast<__half2*>(&u0.x)); v[0] = f.x; v[1] = f.y;
        f = __half22float2(*reinterpret_cast<__half2*>(&u0.y)); v[2] = f.x; v[3] = f.y;
        f = __half22float2(*reinterpret_cast<__half2*>(&u1.x)); v[4] = f.x; v[5] = f.y;
        f = __half22float2(*reinterpret_cast<__half2*>(&u1.y)); v[6] = f.x; v[7] = f.y;
    }

    float m = v[0];
    #pragma unroll
    for (int i = 1; i < 8; i++) m = fmaxf(m, v[i]);
    #pragma unroll
    for (int off = 16; off; off >>= 1) m = fmaxf(m, __shfl_xor_sync(0xffffffffu, m, off));

    __shared__ float redm[8], reds[8];
    if ((t & 31) == 0) redm[t >> 5] = m;
    __syncthreads();
    float bm = redm[0];
    #pragma unroll
    for (int w = 1; w < 8; w++) bm = fmaxf(bm, redm[w]);

    float s = 0.0f;
    #pragma unroll
    for (int i = 0; i < 8; i++) { v[i] = __expf(v[i] - bm); s += v[i]; }
    #pragma unroll
    for (int off = 16; off; off >>= 1) s += __shfl_xor_sync(0xffffffffu, s, off);
    if ((t & 31) == 0) reds[t >> 5] = s;
    __syncthreads();
    float bs = 0.0f;
    #pragma unroll
    for (int w = 0; w < 8; w++) bs += reds[w];

    float inv = 1.0f / bs;
    uint2 o0, o1;
    __half2 h;
    h = __floats2half2_rn(v[0] * inv, v[1] * inv); o0.x = *reinterpret_cast<uint32_t*>(&h);
    h = __floats2half2_rn(v[2] * inv, v[3] * inv); o0.y = *reinterpret_cast<uint32_t*>(&h);
    h = __floats2half2_rn(v[4] * inv, v[5] * inv); o1.x = *reinterpret_cast<uint32_t*>(&h);
    h = __floats2half2_rn(v[6] * inv, v[7] * inv); o1.y = *reinterpret_cast<uint32_t*>(&h);
    pout[t]       = o0;
    pout[t + 256] = o1;
}

// --------------------------- host side -------------------------------------
extern "C" void kernel_launch(void* const* d_in, const int* in_sizes, int n_in,
                              void* d_out, int out_size)
{
    const float* h1 = (const float*)d_in[0];
    const float* h2 = (const float*)d_in[1];
    const float* Wq = (const float*)d_in[2];
    const float* bq = (const float*)d_in[3];
    const float* Wk = (const float*)d_in[4];
    const float* bk = (const float*)d_in[5];
    const float* Wv = (const float*)d_in[6];
    const float* bv = (const float*)d_in[7];
    const float* Wo = (const float*)d_in[8];
    const float* bo = (const float*)d_in[9];
    float* out = (float*)d_out;

    void *h1s, *h2s, *Wqs, *Wks, *Wps, *cb, *tab;
    void *Qs, *Ks, *Vts, *E16, *Es;
    cudaGetSymbolAddress(&h1s, g_h1s);  cudaGetSymbolAddress(&h2s, g_h2s);
    cudaGetSymbolAddress(&Wqs, g_Wqs);  cudaGetSymbolAddress(&Wks, g_Wks);
    cudaGetSymbolAddress(&Wps, g_Wps);  cudaGetSymbolAddress(&cb, g_cb);
    cudaGetSymbolAddress(&tab, g_tab);
    cudaGetSymbolAddress(&Qs, g_Qs);    cudaGetSymbolAddress(&Ks, g_Ks);
    cudaGetSymbolAddress(&Vts, g_Vts);  cudaGetSymbolAddress(&E16, g_E16);
    cudaGetSymbolAddress(&Es, g_Es);

    cudaFuncSetAttribute(gemm_qkv, cudaFuncAttributeMaxDynamicSharedMemorySize, SMEM_G);
    cudaFuncSetAttribute(gemm1<0>, cudaFuncAttributeMaxDynamicSharedMemorySize, SMEM_G);
    cudaFuncSetAttribute(gemm1<1>, cudaFuncAttributeMaxDynamicSharedMemorySize, SMEM_G);

    const float scale = 0.044194173824159216f;  // 1/sqrt(512)

    // 0: prep (h converts + permuted W converts + rope table)
    {
        unsigned blocks = (unsigned)((PREP_TOTAL + 255) / 256);
        prep_kernel<<<blocks, 256>>>(h1, h2, Wq, Wk,
                                     (__half*)h1s, (__half*)h2s,
                                     (__half*)Wqs, (__half*)Wks, (float2*)tab);
    }
    // 1: W' = Wo @ Wv and cb0 = Wo @ bv (one launch)
    {
        dim3 g(DIM / 64, DIM / 64 + 1, 1);
        wfold_kernel<<<g, 256>>>(Wo, Wv, bv, (__half*)Wps, (float*)cb);
    }
    // 2: fused Q/K/V' projections (rope in epilogue; V' written transposed)
    dim3 gqkv(DIM / BN, MS / BM, 3);
    gemm_qkv<<<gqkv, 256, SMEM_G>>>((const __half*)h1s, (const __half*)h2s,
                                    (const __half*)Wqs, (const __half*)Wks,
                                    (const __half*)Wps,
                                    (__half*)Qs, (__half*)Ks, (__half*)Vts,
                                    bq, bk, (const float*)cb, (const float2*)tab);
    // 3: scores E16[b] = scale * Q[b] K[b]^T  (f16 out)
    dim3 ge(SEQ / BN, SEQ / BM, BATCH);
    gemm1<1><<<ge, 256, SMEM_G>>>((const __half*)Qs, (const __half*)Ks,
                                  E16, nullptr, DIM, SEQ, SEQ, SEQ,
                                  (long long)SEQ * SEQ, scale);
    // 4: softmax (f16 -> f16)
    softmax_h_kernel<<<BATCH * SEQ, 256>>>((const __half*)E16, (__half*)Es);
    // 5 (ncu profiles this): out[b] = P[b] Vt[b]^T + bo  (fp32 out, final)
    dim3 gpv(DIM / BN, SEQ / BM, BATCH);
    gemm1<0><<<gpv, 256, SMEM_G>>>((const __half*)Es, (const __half*)Vts,
                                   out, bo, SEQ, DIM, SEQ, DIM,
                                   (long long)SEQ * DIM, 1.0f);
}

// round 17
// speedup vs baseline: 1.2483x; 1.2483x over previous
#include <cuda_runtime.h>
#include <cuda_fp16.h>
#include <stdint.h>
#include <math.h>

// ===========================================================================
// CrossAttention B=8, S=2048, D=512 (single head, fp32 I/O).
// All GEMMs on mma.sync (HMMA fp16, fp32 accum), 1-term, compact f16.
// 128x128 CTA tile, 8 warps (32x64 warp tile), 2 CTAs/SM, register
// double-buffered LDSM fragments. (R16's 256x128/1-CTA variant regressed:
// regs 228, occ 12% -> reverted. Geometry sweep complete; f32-accum HMMA
// issue rate is the binding constraint at ~78% utilization.)
// Algebraic fusions: W'=Wo@Wv fold; RoPE in Q/K epilogue via feature perm;
// V' epilogue writes Vt transposed (conflict-free staging).
// ===========================================================================

#define BATCH 8
#define SEQ   2048
#define DIM   512
#define MS    (BATCH * SEQ)     // 16384
#define HALFD (DIM / 2)

#define BM 128
#define BN 128
#define BKE 64                          // fp16 elems per k-chunk (128 bytes)
#define BKB 128                         // bytes per smem row
#define STAGES 3
#define A_TILE_BYTES (BM * BKB)         // 16384
#define B_TILE_BYTES (BN * BKB)         // 16384
#define STAGE_BYTES (A_TILE_BYTES + B_TILE_BYTES)  // 32768
#define SMEM_G (STAGES * STAGE_BYTES)   // 98304 -> 2 CTAs/SM

// --------------------------- device scratch -------------------------------
__device__ __align__(1024) __half g_h1s[(size_t)MS * DIM];
__device__ __align__(1024) __half g_h2s[(size_t)MS * DIM];
__device__ __align__(1024) __half g_Wqs[(size_t)DIM * DIM];   // permuted rows
__device__ __align__(1024) __half g_Wks[(size_t)DIM * DIM];   // permuted rows
__device__ __align__(1024) __half g_Wps[(size_t)DIM * DIM];   // W' = Wo@Wv
__device__ __align__(1024) float  g_cb[DIM];                  // Wo@bv
__device__ __align__(1024) float2 g_tab[(size_t)SEQ * HALFD]; // (cos,sin)[s][c]
__device__ __align__(1024) __half g_Qs[(size_t)MS * DIM];     // permuted features
__device__ __align__(1024) __half g_Ks[(size_t)MS * DIM];     // permuted features
__device__ __align__(1024) __half g_Vts[(size_t)BATCH * DIM * SEQ];
__device__ __align__(1024) __half g_E16[(size_t)BATCH * SEQ * SEQ];
__device__ __align__(1024) __half g_Es[(size_t)BATCH * SEQ * SEQ];

// --------------------------- PTX helpers -----------------------------------
__device__ __forceinline__ uint32_t smem_u32(const void* p) {
    uint32_t a;
    asm("{ .reg .u64 t; cvta.to.shared.u64 t, %1; cvt.u32.u64 %0, t; }"
        : "=r"(a) : "l"(p));
    return a;
}
__device__ __forceinline__ void cp_async16(uint32_t dst, const void* src) {
    asm volatile("cp.async.cg.shared.global [%0], [%1], 16;" :: "r"(dst), "l"(src));
}
__device__ __forceinline__ void cp_commit() {
    asm volatile("cp.async.commit_group;" ::: "memory");
}
template <int N> __device__ __forceinline__ void cp_wait() {
    asm volatile("cp.async.wait_group %0;" :: "n"(N) : "memory");
}
__device__ __forceinline__ void ldsm4(uint32_t& r0, uint32_t& r1, uint32_t& r2,
                                      uint32_t& r3, uint32_t a) {
    asm volatile("ldmatrix.sync.aligned.m8n8.x4.shared.b16 {%0,%1,%2,%3}, [%4];"
                 : "=r"(r0), "=r"(r1), "=r"(r2), "=r"(r3) : "r"(a));
}
__device__ __forceinline__ void mma16816(float* d, const uint32_t* a,
                                         uint32_t b0, uint32_t b1) {
    asm volatile(
        "mma.sync.aligned.m16n8k16.row.col.f32.f16.f16.f32 "
        "{%0,%1,%2,%3}, {%4,%5,%6,%7}, {%8,%9}, {%0,%1,%2,%3};"
        : "+f"(d[0]), "+f"(d[1]), "+f"(d[2]), "+f"(d[3])
        : "r"(a[0]), "r"(a[1]), "r"(a[2]), "r"(a[3]), "r"(b0), "r"(b1));
}
__device__ __forceinline__ uint32_t sw128(uint32_t off) {
    return off ^ ((off >> 3) & 0x70);
}

// --------------------------- GEMM core (1-term) -----------------------------
// NT: C[m,n] = alpha * A[m,:].B[n,:] + bias[n]
// EPI: 0 = fp32 out, 1 = f16 out, 2 = f16 out with rope rotation (pair cols),
//      3 = f16 out written TRANSPOSED into Vt[B*DIM, SEQ] via smem staging.
// 8 warps: wm = wid&3 (M, 32 rows), wn = wid>>2 (N, 64 cols). acc 64 f32.
// Fragments double-buffered across ks; cp.async refill issued after the
// ks=0 preload so LDSMs aren't queued behind the LSU burst.
template <int EPI>
__device__ __forceinline__ void gemm_core1(
    const __half* __restrict__ A, const __half* __restrict__ B,
    void* __restrict__ Cv, const float* __restrict__ bias,
    const float2* __restrict__ tab,
    int Kp, int ldC, float alpha, int m0, int n0, char* smem)
{
    const int tid  = threadIdx.x;
    const int wid  = tid >> 5;
    const int lane = tid & 31;
    const int wm   = wid & 3;
    const int wn   = wid >> 2;
    const uint32_t smb = smem_u32(smem);
    const int chunks = Kp / BKE;

    auto issue = [&](int it) {
        const long long k0 = (long long)it * BKE;
        const uint32_t sb = smb + (it % STAGES) * STAGE_BYTES;
        #pragma unroll
        for (int i = 0; i < 4; i++) {
            const int id = tid * 4 + i;
            const int r = id >> 3, c = id & 7;
            const uint32_t off = sw128((uint32_t)(r * BKB + c * 16));
            cp_async16(sb + off, A + (long long)r * Kp + k0 + c * 8);
            cp_async16(sb + A_TILE_BYTES + off, B + (long long)r * Kp + k0 + c * 8);
        }
        cp_commit();
    };

    float acc[2][8][4] = {};
    const int aRowBase = wm * 32;
    const int bRowBase = wn * 64;
    const int lrow = lane & 15;
    const int lkc  = lane >> 4;

    const int prol = (chunks < STAGES - 1) ? chunks : (STAGES - 1);
    for (int it = 0; it < prol; it++) issue(it);

    uint32_t a[2][2][4], b[2][4][4];

    for (int it = 0; it < chunks; it++) {
        if (it < chunks - 1) cp_wait<STAGES - 2>(); else cp_wait<0>();
        __syncthreads();

        const uint32_t sA = smb + (it % STAGES) * STAGE_BYTES;
        const uint32_t sB = sA + A_TILE_BYTES;

        // preload ks=0 fragments into buffer 0 (before the refill burst)
        #pragma unroll
        for (int mi = 0; mi < 2; mi++) {
            const int row = aRowBase + mi * 16 + lrow;
            const uint32_t off = sw128((uint32_t)(row * BKB + lkc * 16));
            ldsm4(a[0][mi][0], a[0][mi][1], a[0][mi][2], a[0][mi][3], sA + off);
        }
        #pragma unroll
        for (int nt = 0; nt < 4; nt++) {
            const int row = bRowBase + nt * 16 + lrow;
            const uint32_t off = sw128((uint32_t)(row * BKB + lkc * 16));
            ldsm4(b[0][nt][0], b[0][nt][1], b[0][nt][2], b[0][nt][3], sB + off);
        }

        // refill the stage consumed (STAGES-1) iters ago
        if (it + STAGES - 1 < chunks) issue(it + STAGES - 1);

        #pragma unroll
        for (int ks = 0; ks < 4; ks++) {
            const int cur = ks & 1;
            if (ks < 3) {                      // prefetch ks+1 before MMAs
                const int nxt = cur ^ 1;
                #pragma unroll
                for (int mi = 0; mi < 2; mi++) {
                    const int row = aRowBase + mi * 16 + lrow;
                    const uint32_t off =
                        sw128((uint32_t)(row * BKB + (ks + 1) * 32 + lkc * 16));
                    ldsm4(a[nxt][mi][0], a[nxt][mi][1], a[nxt][mi][2], a[nxt][mi][3],
                          sA + off);
                }
                #pragma unroll
                for (int nt = 0; nt < 4; nt++) {
                    const int row = bRowBase + nt * 16 + lrow;
                    const uint32_t off =
                        sw128((uint32_t)(row * BKB + (ks + 1) * 32 + lkc * 16));
                    ldsm4(b[nxt][nt][0], b[nxt][nt][1], b[nxt][nt][2], b[nxt][nt][3],
                          sB + off);
                }
            }
            #pragma unroll
            for (int mi = 0; mi < 2; mi++)
                #pragma unroll
                for (int nt = 0; nt < 4; nt++) {
                    mma16816(acc[mi][nt * 2],     a[cur][mi], b[cur][nt][0], b[cur][nt][2]);
                    mma16816(acc[mi][nt * 2 + 1], a[cur][mi], b[cur][nt][1], b[cur][nt][3]);
                }
        }
    }

    if (EPI == 3) {
        // Stage f16 tile TRANSPOSED in smem (sm[n][m], PR=132), then
        // coalesced write to Vt[B*DIM, SEQ]. All cp.async complete (wait<0>).
        __syncthreads();
        __half* sm = (__half*)smem;
        const int PR = 132;
        #pragma unroll
        for (int mi = 0; mi < 2; mi++) {
            const int rl = wm * 32 + mi * 16 + (lane >> 2);
            #pragma unroll
            for (int nj = 0; nj < 8; nj++) {
                const int cl = wn * 64 + nj * 8 + (lane & 3) * 2;
                float b0 = bias[n0 + cl];
                float b1 = bias[n0 + cl + 1];
                sm[cl * PR + rl]           = __float2half(acc[mi][nj][0] + b0);
                sm[(cl + 1) * PR + rl]     = __float2half(acc[mi][nj][1] + b1);
                sm[cl * PR + rl + 8]       = __float2half(acc[mi][nj][2] + b0);
                sm[(cl + 1) * PR + rl + 8] = __float2half(acc[mi][nj][3] + b1);
            }
        }
        __syncthreads();
        __half* Vt = (__half*)Cv;
        const int bz = m0 >> 11;               // batch (m0 / SEQ)
        const int s0 = m0 & (SEQ - 1);
        #pragma unroll
        for (int jj = 0; jj < 16; jj++) {
            const int j = wid * 16 + jj;       // feature col 0..127
            __half t0 = sm[j * PR + lane * 4 + 0];
            __half t1 = sm[j * PR + lane * 4 + 1];
            __half t2 = sm[j * PR + lane * 4 + 2];
            __half t3 = sm[j * PR + lane * 4 + 3];
            uint2 u;
            __half2 h01 = __halves2half2(t0, t1);
            __half2 h23 = __halves2half2(t2, t3);
            u.x = *reinterpret_cast<uint32_t*>(&h01);
            u.y = *reinterpret_cast<uint32_t*>(&h23);
            *reinterpret_cast<uint2*>(Vt + (size_t)bz * DIM * SEQ
                                      + (size_t)(n0 + j) * SEQ + s0 + lane * 4) = u;
        }
        return;
    }

    #pragma unroll
    for (int mi = 0; mi < 2; mi++) {
        const int r = m0 + wm * 32 + mi * 16 + (lane >> 2);
        const int s0 = r & (SEQ - 1);
        const int s1 = (r + 8) & (SEQ - 1);
        #pragma unroll
        for (int nj = 0; nj < 8; nj++) {
            const int cidx = n0 + wn * 64 + nj * 8 + (lane & 3) * 2;
            if (EPI == 2) {
                const int c = cidx >> 1;
                float b0 = bias ? bias[c] : 0.f;
                float b1 = bias ? bias[c + HALFD] : 0.f;
                float x0 = acc[mi][nj][0] + b0;
                float x1 = acc[mi][nj][1] + b1;
                float x2 = acc[mi][nj][2] + b0;
                float x3 = acc[mi][nj][3] + b1;
                float2 cs0 = tab[(size_t)s0 * HALFD + c];
                float2 cs1 = tab[(size_t)s1 * HALFD + c];
                float y0 = x0 * cs0.x - x1 * cs0.y;
                float y1 = x1 * cs0.x + x0 * cs0.y;
                float y2 = x2 * cs1.x - x3 * cs1.y;
                float y3 = x3 * cs1.x + x2 * cs1.y;
                __half* Ch = (__half*)Cv;
                *reinterpret_cast<__half2*>(Ch + (long long)r * ldC + cidx)
                    = __floats2half2_rn(y0, y1);
                *reinterpret_cast<__half2*>(Ch + (long long)(r + 8) * ldC + cidx)
                    = __floats2half2_rn(y2, y3);
            } else {
                float b0 = bias ? bias[cidx] : 0.f;
                float b1 = bias ? bias[cidx + 1] : 0.f;
                float x0 = acc[mi][nj][0] * alpha + b0;
                float x1 = acc[mi][nj][1] * alpha + b1;
                float x2 = acc[mi][nj][2] * alpha + b0;
                float x3 = acc[mi][nj][3] * alpha + b1;
                if (EPI == 0) {
                    float* Cf = (float*)Cv;
                    *reinterpret_cast<float2*>(Cf + (long long)r * ldC + cidx)
                        = make_float2(x0, x1);
                    *reinterpret_cast<float2*>(Cf + (long long)(r + 8) * ldC + cidx)
                        = make_float2(x2, x3);
                } else {
                    __half* Ch = (__half*)Cv;
                    *reinterpret_cast<__half2*>(Ch + (long long)r * ldC + cidx)
                        = __floats2half2_rn(x0, x1);
                    *reinterpret_cast<__half2*>(Ch + (long long)(r + 8) * ldC + cidx)
                        = __floats2half2_rn(x2, x3);
                }
            }
        }
    }
}

// Generic batched GEMM (EPI 0 = fp32 out, 1 = f16 out), 2 CTAs/SM.
template <int EPI>
__global__ __launch_bounds__(256, 2) void gemm1(
    const __half* __restrict__ A, const __half* __restrict__ B,
    void* __restrict__ C, const float* __restrict__ bias,
    int Kp, int ldC, int aRowsPerB, int bRowsPerB, long long cPerB, float alpha)
{
    extern __shared__ __align__(1024) char smem[];
    const __half* Ab = A + ((long long)blockIdx.z * aRowsPerB + (long long)blockIdx.y * BM) * Kp;
    const __half* Bb = B + ((long long)blockIdx.z * bRowsPerB + (long long)blockIdx.x * BN) * Kp;
    void* Cb = (EPI == 0)
        ? (void*)((float*)C + (long long)blockIdx.z * cPerB)
        : (void*)((__half*)C + (long long)blockIdx.z * cPerB);
    gemm_core1<EPI>(Ab, Bb, Cb, bias, nullptr, Kp, ldC, alpha,
                    blockIdx.y * BM, blockIdx.x * BN, smem);
}

// Fused Q/K/V' projections. z=0: Q=rope(h1@Wq^T+bq); z=1: K likewise;
// z=2: Vt = transpose(h2@W'^T + cb0) written directly.
__global__ __launch_bounds__(256, 2) void gemm_qkv(
    const __half* __restrict__ h1s, const __half* __restrict__ h2s,
    const __half* __restrict__ Wq, const __half* __restrict__ Wk,
    const __half* __restrict__ Wp,
    __half* __restrict__ Qs, __half* __restrict__ Ks, __half* __restrict__ Vts,
    const float* __restrict__ bq, const float* __restrict__ bk,
    const float* __restrict__ cb0, const float2* __restrict__ tab)
{
    extern __shared__ __align__(1024) char smem[];
    const int m0 = blockIdx.y * BM, n0 = blockIdx.x * BN;
    if (blockIdx.z == 2) {
        const __half* A = h2s + (long long)m0 * DIM;
        const __half* B = Wp + (long long)n0 * DIM;
        gemm_core1<3>(A, B, Vts, cb0, nullptr, DIM, 0, 1.0f, m0, n0, smem);
    } else {
        const __half* A = (blockIdx.z == 0 ? h1s : h2s) + (long long)m0 * DIM;
        const __half* B = (blockIdx.z == 0 ? Wq : Wk) + (long long)n0 * DIM;
        __half* C = blockIdx.z == 0 ? Qs : Ks;
        const float* bias = blockIdx.z == 0 ? bq : bk;
        gemm_core1<2>(A, B, C, bias, tab, DIM, DIM, 1.0f, m0, n0, smem);
    }
}

// ---------------- weight folding + cbias (fp32 exact), one launch ----------
__global__ __launch_bounds__(256) void wfold_kernel(
    const float* __restrict__ Wo, const float* __restrict__ Wv,
    const float* __restrict__ bv,
    __half* __restrict__ Wps, float* __restrict__ cb)
{
    const int t = threadIdx.x;
    if (blockIdx.y == DIM / 64) {
        const int w = t >> 5, lane = t & 31;
        #pragma unroll
        for (int k = 0; k < 8; k++) {
            const int e = blockIdx.x * 64 + w + k * 8;
            float s = 0.f;
            for (int d = lane; d < DIM; d += 32) s += Wo[e * DIM + d] * bv[d];
            #pragma unroll
            for (int off = 16; off; off >>= 1) s += __shfl_xor_sync(0xffffffffu, s, off);
            if (lane == 0) cb[e] = s;
        }
        return;
    }
    __shared__ float As[16][64];
    __shared__ float Bs[16][64];
    const int tx = t & 15, ty = t >> 4;
    const int e0 = blockIdx.y * 64;
    const int c0 = blockIdx.x * 64;

    float acc[4][4] = {};
    for (int d0 = 0; d0 < DIM; d0 += 16) {
        #pragma unroll
        for (int i = 0; i < 4; i++) {
            int id = t * 4 + i;
            int m = id >> 4, dd = id & 15;
            As[dd][m] = Wo[(e0 + m) * DIM + d0 + dd];
            int col = id & 63, row = id >> 6;
            Bs[row][col] = Wv[(d0 + row) * DIM + c0 + col];
        }
        __syncthreads();
        #pragma unroll
        for (int dd = 0; dd < 16; dd++) {
            float a[4], b[4];
            #pragma unroll
            for (int u = 0; u < 4; u++) { a[u] = As[dd][ty * 4 + u]; b[u] = Bs[dd][tx * 4 + u]; }
            #pragma unroll
            for (int x = 0; x < 4; x++)
                #pragma unroll
                for (int y = 0; y < 4; y++)
                    acc[x][y] = fmaf(a[x], b[y], acc[x][y]);
        }
        __syncthreads();
    }
    #pragma unroll
    for (int x = 0; x < 4; x++)
        #pragma unroll
        for (int y = 0; y < 4; y++)
            Wps[(size_t)(e0 + ty * 4 + x) * DIM + c0 + tx * 4 + y] = __float2half(acc[x][y]);
}

// ---------------- prep: h converts + permuted W converts + rope table ------
#define N4_H  ((long long)MS * DIM / 4)
#define N4_W  ((long long)DIM * DIM / 4)
#define N_TAB ((long long)SEQ * HALFD)
#define PREP_TOTAL (2 * N4_H + 2 * N4_W + N_TAB)

__global__ void prep_kernel(const float* __restrict__ h1, const float* __restrict__ h2,
                            const float* __restrict__ wq, const float* __restrict__ wk,
                            __half* __restrict__ h1s, __half* __restrict__ h2s,
                            __half* __restrict__ yq, __half* __restrict__ yk,
                            float2* __restrict__ tab)
{
    long long i = (long long)blockIdx.x * blockDim.x + threadIdx.x;
    if (i < 2 * N4_H) {
        const float* src = (i < N4_H) ? h1 : h2;
        __half* dst = (i < N4_H) ? h1s : h2s;
        long long k = (i < N4_H) ? i : i - N4_H;
        float4 v = reinterpret_cast<const float4*>(src)[k];
        reinterpret_cast<__half2*>(dst)[k * 2]     = __floats2half2_rn(v.x, v.y);
        reinterpret_cast<__half2*>(dst)[k * 2 + 1] = __floats2half2_rn(v.z, v.w);
        return;
    }
    i -= 2 * N4_H;
    if (i < 2 * N4_W) {
        const float* src = (i < N4_W) ? wq : wk;
        __half* dst = (i < N4_W) ? yq : yk;
        long long k = (i < N4_W) ? i : i - N4_W;
        int p = (int)(k / (DIM / 4));
        int d4 = (int)(k % (DIM / 4));
        int orig = (p & 1) ? (p >> 1) + HALFD : (p >> 1);
        float4 v = reinterpret_cast<const float4*>(src + (size_t)orig * DIM)[d4];
        __half2* o = reinterpret_cast<__half2*>(dst + (size_t)p * DIM) + d4 * 2;
        o[0] = __floats2half2_rn(v.x, v.y);
        o[1] = __floats2half2_rn(v.z, v.w);
        return;
    }
    i -= 2 * N4_W;
    if (i < N_TAB) {
        int c = (int)(i % HALFD);
        int s = (int)(i / HALFD);
        const float kNegLog2Base = -13.287712379549449f / 256.0f;
        float invf = exp2f((float)c * kNegLog2Base);
        float sn, cs;
        sincosf((float)s * invf, &sn, &cs);
        tab[i] = make_float2(cs, sn);
    }
}

// ---------------- softmax (f16 in/out, 8 halves/thread) ---------------------
__global__ __launch_bounds__(256) void softmax_h_kernel(const __half* __restrict__ E,
                                                        __half* __restrict__ Es)
{
    const int t = threadIdx.x;
    const uint2* pin = reinterpret_cast<const uint2*>(E + (size_t)blockIdx.x * SEQ);
    uint2* pout = reinterpret_cast<uint2*>(Es + (size_t)blockIdx.x * SEQ);

    uint2 u0 = pin[t];
    uint2 u1 = pin[t + 256];
    float v[8];
    {
        float2 f;
        f = __half22float2(*reinterpret_cast<__half2*>(&u0.x)); v[0] = f.x; v[1] = f.y;
        f = __half22float2(*reinterpret_cast<__half2*>(&u0.y)); v[2] = f.x; v[3] = f.y;
        f = __half22float2(*reinterpret_cast<__half2*>(&u1.x)); v[4] = f.x; v[5] = f.y;
        f = __half22float2(*reinterpret_cast<__half2*>(&u1.y)); v[6] = f.x; v[7] = f.y;
    }

    float m = v[0];
    #pragma unroll
    for (int i = 1; i < 8; i++) m = fmaxf(m, v[i]);
    #pragma unroll
    for (int off = 16; off; off >>= 1) m = fmaxf(m, __shfl_xor_sync(0xffffffffu, m, off));

    __shared__ float redm[8], reds[8];
    if ((t & 31) == 0) redm[t >> 5] = m;
    __syncthreads();
    float bm = redm[0];
    #pragma unroll
    for (int w = 1; w < 8; w++) bm = fmaxf(bm, redm[w]);

    float s = 0.0f;
    #pragma unroll
    for (int i = 0; i < 8; i++) { v[i] = __expf(v[i] - bm); s += v[i]; }
    #pragma unroll
    for (int off = 16; off; off >>= 1) s += __shfl_xor_sync(0xffffffffu, s, off);
    if ((t & 31) == 0) reds[t >> 5] = s;
    __syncthreads();
    float bs = 0.0f;
    #pragma unroll
    for (int w = 0; w < 8; w++) bs += reds[w];

    float inv = 1.0f / bs;
    uint2 o0, o1;
    __half2 h;
    h = __floats2half2_rn(v[0] * inv, v[1] * inv); o0.x = *reinterpret_cast<uint32_t*>(&h);
    h = __floats2half2_rn(v[2] * inv, v[3] * inv); o0.y = *reinterpret_cast<uint32_t*>(&h);
    h = __floats2half2_rn(v[4] * inv, v[5] * inv); o1.x = *reinterpret_cast<uint32_t*>(&h);
    h = __floats2half2_rn(v[6] * inv, v[7] * inv); o1.y = *reinterpret_cast<uint32_t*>(&h);
    pout[t]       = o0;
    pout[t + 256] = o1;
}

// --------------------------- host side -------------------------------------
extern "C" void kernel_launch(void* const* d_in, const int* in_sizes, int n_in,
                              void* d_out, int out_size)
{
    const float* h1 = (const float*)d_in[0];
    const float* h2 = (const float*)d_in[1];
    const float* Wq = (const float*)d_in[2];
    const float* bq = (const float*)d_in[3];
    const float* Wk = (const float*)d_in[4];
    const float* bk = (const float*)d_in[5];
    const float* Wv = (const float*)d_in[6];
    const float* bv = (const float*)d_in[7];
    const float* Wo = (const float*)d_in[8];
    const float* bo = (const float*)d_in[9];
    float* out = (float*)d_out;

    void *h1s, *h2s, *Wqs, *Wks, *Wps, *cb, *tab;
    void *Qs, *Ks, *Vts, *E16, *Es;
    cudaGetSymbolAddress(&h1s, g_h1s);  cudaGetSymbolAddress(&h2s, g_h2s);
    cudaGetSymbolAddress(&Wqs, g_Wqs);  cudaGetSymbolAddress(&Wks, g_Wks);
    cudaGetSymbolAddress(&Wps, g_Wps);  cudaGetSymbolAddress(&cb, g_cb);
    cudaGetSymbolAddress(&tab, g_tab);
    cudaGetSymbolAddress(&Qs, g_Qs);    cudaGetSymbolAddress(&Ks, g_Ks);
    cudaGetSymbolAddress(&Vts, g_Vts);  cudaGetSymbolAddress(&E16, g_E16);
    cudaGetSymbolAddress(&Es, g_Es);

    cudaFuncSetAttribute(gemm_qkv, cudaFuncAttributeMaxDynamicSharedMemorySize, SMEM_G);
    cudaFuncSetAttribute(gemm1<0>, cudaFuncAttributeMaxDynamicSharedMemorySize, SMEM_G);
    cudaFuncSetAttribute(gemm1<1>, cudaFuncAttributeMaxDynamicSharedMemorySize, SMEM_G);

    const float scale = 0.044194173824159216f;  // 1/sqrt(512)

    // 0: prep (h converts + permuted W converts + rope table)
    {
        unsigned blocks = (unsigned)((PREP_TOTAL + 255) / 256);
        prep_kernel<<<blocks, 256>>>(h1, h2, Wq, Wk,
                                     (__half*)h1s, (__half*)h2s,
                                     (__half*)Wqs, (__half*)Wks, (float2*)tab);
    }
    // 1: W' = Wo @ Wv and cb0 = Wo @ bv (one launch)
    {
        dim3 g(DIM / 64, DIM / 64 + 1, 1);
        wfold_kernel<<<g, 256>>>(Wo, Wv, bv, (__half*)Wps, (float*)cb);
    }
    // 2: fused Q/K/V' projections (rope in epilogue; V' written transposed)
    dim3 gqkv(DIM / BN, MS / BM, 3);
    gemm_qkv<<<gqkv, 256, SMEM_G>>>((const __half*)h1s, (const __half*)h2s,
                                    (const __half*)Wqs, (const __half*)Wks,
                                    (const __half*)Wps,
                                    (__half*)Qs, (__half*)Ks, (__half*)Vts,
                                    bq, bk, (const float*)cb, (const float2*)tab);
    // 3: scores E16[b] = scale * Q[b] K[b]^T  (f16 out)
    dim3 ge(SEQ / BN, SEQ / BM, BATCH);
    gemm1<1><<<ge, 256, SMEM_G>>>((const __half*)Qs, (const __half*)Ks,
                                  E16, nullptr, DIM, SEQ, SEQ, SEQ,
                                  (long long)SEQ * SEQ, scale);
    // 4: softmax (f16 -> f16)
    softmax_h_kernel<<<BATCH * SEQ, 256>>>((const __half*)E16, (__half*)Es);
    // 5: out[b] = P[b] Vt[b]^T + bo  (fp32 out, final)
    dim3 gpv(DIM / BN, SEQ / BM, BATCH);
    gemm1<0><<<gpv, 256, SMEM_G>>>((const __half*)Es, (const __half*)Vts,
                                   out, bo, SEQ, DIM, SEQ, DIM,
                                   (long long)SEQ * DIM, 1.0f);
}